// round 12
// baseline (speedup 1.0000x reference)
#include <cuda_runtime.h>
#include <cstdint>

// Problem constants
#define BATCH 64
#define NNODE 32
#define CH    512
#define HW    49
#define ROWS  (BATCH * NNODE * CH)     // 1,048,576 pooled rows of 49 floats
#define SROWS (BATCH * NNODE)          // 2048 rows of state / T

// Pooling pipeline: 3-stage TMA-bulk ring, 64-row chunks (12544 B each)
#define CHUNK_ROWS 64
#define CHUNK_BYTES (CHUNK_ROWS * HW * 4)      // 12544, multiple of 16
#define CHUNKS_PER_BLK 16
#define POOL_BLKS (ROWS / (CHUNK_ROWS * CHUNKS_PER_BLK))   // 1024
#define NSTAGE 3
#define UV_BLKS 16
#define POOL_BID0 (64 + UV_BLKS)               // pooling starts at block 80

typedef unsigned long long ull;

// Scratch (device globals; no allocation allowed)
__device__ float g_state[SROWS * CH];  // 4 MB  state[b*32+n][c]
__device__ float g_T[SROWS * CH];      // 4 MB  T = state @ M
__device__ float g_M[CH * CH];         // 1 MB  M = W1^T W2
__device__ float g_u[CH];              // u = W1^T b2
__device__ float g_v[CH];              // v = W2^T b1
__device__ float g_c0;                 // b1 . b2

// ---- packed f32x2 helpers (sm_100+) ----
__device__ __forceinline__ ull dupf(float v) {
    ull r; asm("mov.b64 %0, {%1, %1};" : "=l"(r) : "f"(v)); return r;
}
__device__ __forceinline__ ull packf(float lo, float hi) {
    ull r; asm("mov.b64 %0, {%1, %2};" : "=l"(r) : "f"(lo), "f"(hi)); return r;
}
__device__ __forceinline__ void fma2(ull& d, ull a, ull b) {
    asm("fma.rn.f32x2 %0, %1, %2, %0;" : "+l"(d) : "l"(a), "l"(b));
}
__device__ __forceinline__ void unpackf(ull p, float& lo, float& hi) {
    asm("mov.b64 {%0, %1}, %2;" : "=f"(lo), "=f"(hi) : "l"(p));
}

// ---- mbarrier + bulk-async helpers ----
__device__ __forceinline__ void mbar_init(uint32_t addr, uint32_t cnt) {
    asm volatile("mbarrier.init.shared.b64 [%0], %1;" :: "r"(addr), "r"(cnt) : "memory");
}
__device__ __forceinline__ void mbar_expect_tx(uint32_t addr, uint32_t bytes) {
    asm volatile("mbarrier.arrive.expect_tx.shared.b64 _, [%0], %1;"
                 :: "r"(addr), "r"(bytes) : "memory");
}
__device__ __forceinline__ void mbar_wait(uint32_t addr, uint32_t phase) {
    uint32_t done;
    asm volatile(
        "{\n\t.reg .pred p;\n\t"
        "mbarrier.try_wait.parity.acquire.cta.shared::cta.b64 p, [%1], %2;\n\t"
        "selp.b32 %0, 1, 0, p;\n\t}"
        : "=r"(done) : "r"(addr), "r"(phase) : "memory");
    if (!done) {
        asm volatile(
            "{\n\t.reg .pred P1;\n\t"
            "WL_%=:\n\t"
            "mbarrier.try_wait.parity.acquire.cta.shared::cta.b64 P1, [%0], %1, 0x989680;\n\t"
            "@P1 bra.uni WD_%=;\n\t"
            "bra.uni WL_%=;\n\t"
            "WD_%=:\n\t}"
            :: "r"(addr), "r"(phase) : "memory");
    }
}
__device__ __forceinline__ void bulk_ld(uint32_t dst_smem, const void* src_gmem,
                                        uint32_t bytes, uint32_t mbar) {
    asm volatile(
        "cp.async.bulk.shared::cluster.global.mbarrier::complete_tx::bytes "
        "[%0], [%1], %2, [%3];"
        :: "r"(dst_smem), "l"(src_gmem), "r"(bytes), "r"(mbar) : "memory");
}
__device__ __forceinline__ void fence_proxy_async_cta() {
    asm volatile("fence.proxy.async.shared::cta;" ::: "memory");
}

// ---------------------------------------------------------------------------
// Kernel 1: blocks [0,64)   -> M = W1^T W2 (64x64 tiles)
//           blocks [64,80)  -> u, v (32 columns each); block 64 also c0
//           blocks [80,..)  -> pooling: 3-stage cp.async.bulk pipeline
// ---------------------------------------------------------------------------
__global__ void __launch_bounds__(256) k1_pool_prep(
    const float* __restrict__ x,
    const float* __restrict__ W1, const float* __restrict__ b1,
    const float* __restrict__ W2, const float* __restrict__ b2)
{
    __shared__ __align__(16) union {
        struct { float As[16][64]; float Bs[16][64]; } gemm;          // 8 KB
        struct { float ru[8][33]; float rv[8][33]; } uv;              // ~2 KB
        struct {
            float buf[NSTAGE][CHUNK_ROWS * HW];                       // 37632 B
            unsigned long long mbar[NSTAGE];
        } pool;
    } smem;

    const int bid = blockIdx.x;
    const int tid = threadIdx.x;

    if (bid < 64) {
        // ---- M = W1^T W2 : M[i,j] = sum_k W1[k,i] * W2[k,j] ----
        float (*As)[64] = smem.gemm.As;
        float (*Bs)[64] = smem.gemm.Bs;
        const int j0 = (bid & 7) * 64;
        const int i0 = (bid >> 3) * 64;
        const int lkk = tid >> 4;            // 0..15
        const int lj4 = (tid & 15) * 4;      // 0..60
        const int ty = tid >> 4, tx = tid & 15;
        float acc[4][4];
        #pragma unroll
        for (int i = 0; i < 4; i++)
            #pragma unroll
            for (int j = 0; j < 4; j++) acc[i][j] = 0.f;

        for (int kc = 0; kc < CH; kc += 16) {
            float4 a4 = *(const float4*)&W1[(kc + lkk) * CH + i0 + lj4];
            float4 b4 = *(const float4*)&W2[(kc + lkk) * CH + j0 + lj4];
            *(float4*)&As[lkk][lj4] = a4;
            *(float4*)&Bs[lkk][lj4] = b4;
            __syncthreads();
            #pragma unroll
            for (int kk = 0; kk < 16; kk++) {
                float4 a = *(const float4*)&As[kk][ty * 4];
                float4 b = *(const float4*)&Bs[kk][tx * 4];
                float av[4] = {a.x, a.y, a.z, a.w};
                float bv[4] = {b.x, b.y, b.z, b.w};
                #pragma unroll
                for (int i = 0; i < 4; i++)
                    #pragma unroll
                    for (int j = 0; j < 4; j++)
                        acc[i][j] = fmaf(av[i], bv[j], acc[i][j]);
            }
            __syncthreads();
        }
        #pragma unroll
        for (int i = 0; i < 4; i++) {
            float4 o = make_float4(acc[i][0], acc[i][1], acc[i][2], acc[i][3]);
            *(float4*)&g_M[(i0 + ty * 4 + i) * CH + j0 + tx * 4] = o;
        }
        return;
    }

    if (bid < POOL_BID0) {
        // ---- u/v: 16 blocks, 32 columns each, 8-way d-split ----
        const int j = bid - 64;          // 0..15
        const int i = j * 32 + (tid & 31);
        const int dg = tid >> 5;         // 0..7
        float au = 0.f, av = 0.f;
        #pragma unroll 8
        for (int d = dg; d < CH; d += 8) {
            float bb2 = b2[d], bb1 = b1[d];
            au = fmaf(W1[d * CH + i], bb2, au);
            av = fmaf(W2[d * CH + i], bb1, av);
        }
        smem.uv.ru[dg][tid & 31] = au;
        smem.uv.rv[dg][tid & 31] = av;
        __syncthreads();
        if (tid < 32) {
            float su = 0.f, sv = 0.f;
            #pragma unroll
            for (int g = 0; g < 8; g++) { su += smem.uv.ru[g][tid]; sv += smem.uv.rv[g][tid]; }
            g_u[j * 32 + tid] = su;
            g_v[j * 32 + tid] = sv;
        }
        // c0 = b1.b2 (block 64, warp 1, deterministic lane order)
        if (j == 0 && (tid >> 5) == 1) {
            const int lane = tid & 31;
            float c = 0.f;
            #pragma unroll
            for (int d = lane; d < CH; d += 32) c = fmaf(b1[d], b2[d], c);
            #pragma unroll
            for (int o = 16; o; o >>= 1) c += __shfl_xor_sync(0xFFFFFFFFu, c, o);
            if (lane == 0) g_c0 = c;
        }
        return;
    }

    // ---- Pooling: 3-stage cp.async.bulk pipeline ----
    {
        const int pb = bid - POOL_BID0;                // 0..1023
        const int chunk0 = pb * CHUNKS_PER_BLK;

        uint32_t sbuf[NSTAGE], smb[NSTAGE];
        #pragma unroll
        for (int s = 0; s < NSTAGE; s++) {
            sbuf[s] = (uint32_t)__cvta_generic_to_shared(&smem.pool.buf[s][0]);
            smb[s]  = (uint32_t)__cvta_generic_to_shared(&smem.pool.mbar[s]);
        }

        if (tid == 0) {
            #pragma unroll
            for (int s = 0; s < NSTAGE; s++) mbar_init(smb[s], 1);
            fence_proxy_async_cta();
        }
        __syncthreads();

        auto issue = [&](int c) {
            const int st = c % NSTAGE;
            mbar_expect_tx(smb[st], CHUNK_BYTES);
            bulk_ld(sbuf[st],
                    x + (size_t)(chunk0 + c) * CHUNK_ROWS * HW,
                    CHUNK_BYTES, smb[st]);
        };

        if (tid == 0) { issue(0); issue(1); issue(2); }

        const int row = tid >> 2;       // 0..63
        const int sub = tid & 3;        // quarter-row selector

        #pragma unroll
        for (int c = 0; c < CHUNKS_PER_BLK; c++) {
            mbar_wait(smb[c % NSTAGE], (c / NSTAGE) & 1);

            const float* __restrict__ r = &smem.pool.buf[c % NSTAGE][row * HW];
            float s = 0.f;
            #pragma unroll
            for (int k = sub; k < HW; k += 4) s += r[k];
            s += __shfl_xor_sync(0xFFFFFFFFu, s, 1);
            s += __shfl_xor_sync(0xFFFFFFFFu, s, 2);
            if (sub == 0)
                g_state[(size_t)(chunk0 + c) * CHUNK_ROWS + row] = s * (1.f / 49.f);

            __syncthreads();            // all reads of stage c%NSTAGE done
            if (tid == 0 && c + NSTAGE < CHUNKS_PER_BLK)
                issue(c + NSTAGE);      // refill the stage just drained
        }
    }
}

// ---------------------------------------------------------------------------
// Kernel 2: T = S @ M  (2048x512 @ 512x512), 64x64 tiles, 4x4 microtiles,
// packed fma.rn.f32x2 on the j-dimension (2 MACs/instr on the FMA pipe).
// ---------------------------------------------------------------------------
__global__ void __launch_bounds__(256) k2_gemmT()
{
    __shared__ __align__(16) float As[16][68];  // transposed S tile, padded
    __shared__ __align__(16) float Bs[16][64];

    const int tid = threadIdx.x;
    const int j0 = (blockIdx.x & 7) * 64;       // over CH (512/64 = 8)
    const int r0 = (blockIdx.x >> 3) * 64;      // over SROWS (2048/64 = 32)

    const int a_i = tid >> 2;                   // 0..63 (row within tile)
    const int a_k = (tid & 3) * 4;              // 0,4,8,12
    const int lkk = tid >> 4;                   // 0..15
    const int lj4 = (tid & 15) * 4;
    const int ty = tid >> 4, tx = tid & 15;

    ull acc2[4][2];                             // [i][j-pair], 2 floats each
    #pragma unroll
    for (int i = 0; i < 4; i++) { acc2[i][0] = 0ull; acc2[i][1] = 0ull; }

    for (int kc = 0; kc < CH; kc += 16) {
        float4 av4 = *(const float4*)&g_state[(r0 + a_i) * CH + kc + a_k];
        float4 bv4 = *(const float4*)&g_M[(kc + lkk) * CH + j0 + lj4];
        As[a_k + 0][a_i] = av4.x;
        As[a_k + 1][a_i] = av4.y;
        As[a_k + 2][a_i] = av4.z;
        As[a_k + 3][a_i] = av4.w;
        *(float4*)&Bs[lkk][lj4] = bv4;
        __syncthreads();
        #pragma unroll
        for (int kk = 0; kk < 16; kk++) {
            float4 a = *(const float4*)&As[kk][ty * 4];
            float4 b = *(const float4*)&Bs[kk][tx * 4];
            ull b01 = packf(b.x, b.y);
            ull b23 = packf(b.z, b.w);
            ull ad[4] = {dupf(a.x), dupf(a.y), dupf(a.z), dupf(a.w)};
            #pragma unroll
            for (int i = 0; i < 4; i++) {
                fma2(acc2[i][0], ad[i], b01);
                fma2(acc2[i][1], ad[i], b23);
            }
        }
        __syncthreads();
    }
    #pragma unroll
    for (int i = 0; i < 4; i++) {
        float4 o;
        unpackf(acc2[i][0], o.x, o.y);
        unpackf(acc2[i][1], o.z, o.w);
        *(float4*)&g_T[(r0 + ty * 4 + i) * CH + j0 + tx * 4] = o;
    }
}

// ---------------------------------------------------------------------------
// Kernel 3: one block per batch.
//   adj[n,m] = T[b,n,:].S[b,m,:] + su[n] + sv[m] + c0
//   z = (adj - mean)/std(ddof=1); soft = row softmax(z)
//   out[b,c] = sum_m (colmean(soft)[m] + 1/32) * S[b,m,c]
// adj dots use f32x2 packed along k (even/odd lanes, horizontal add at end).
// ---------------------------------------------------------------------------
__global__ void __launch_bounds__(256) k3_finale(float* __restrict__ out)
{
    __shared__ float adj[32][36];
    __shared__ float adjp[4][32][36];
    __shared__ float su[32], sv[32], qw[32];
    __shared__ float redS[8], redQ[8];
    __shared__ float stats[2];

    const int b = blockIdx.x;
    const int tid = threadIdx.x;
    const int w = tid >> 5;
    const int lane = tid & 31;

    const float* sb = g_state + (size_t)(b * NNODE) * CH;
    const float* tb = g_T + (size_t)(b * NNODE) * CH;

    // --- su[n] = s[n].u ; sv[n] = s[n].v  (warp per 4 rows) ---
    #pragma unroll
    for (int rr = 0; rr < 4; rr++) {
        int n = w * 4 + rr;
        const float* srow = sb + n * CH;
        float au = 0.f, av = 0.f;
        for (int k = lane; k < CH; k += 32) {
            float s = srow[k];
            au = fmaf(s, g_u[k], au);
            av = fmaf(s, g_v[k], av);
        }
        #pragma unroll
        for (int o = 16; o; o >>= 1) {
            au += __shfl_xor_sync(0xFFFFFFFFu, au, o);
            av += __shfl_xor_sync(0xFFFFFFFFu, av, o);
        }
        if (lane == 0) { su[n] = au; sv[n] = av; }
    }
    __syncthreads();

    // --- adj bias init ---
    const float c0 = g_c0;
    #pragma unroll
    for (int e = tid; e < 1024; e += 256)
        adj[e >> 5][e & 31] = su[e >> 5] + sv[e & 31] + c0;

    // --- adj partial dots: 4x4 register blocks, k split in 4, f32x2 packed ---
    {
        const int rg = tid & 63, g = tid >> 6;
        const int n0 = (rg >> 3) * 4, m0 = (rg & 7) * 4;
        ull c2[4][4];
        #pragma unroll
        for (int i = 0; i < 4; i++)
            #pragma unroll
            for (int j = 0; j < 4; j++) c2[i][j] = 0ull;

        const int k0 = g * 128, k1 = k0 + 128;
        for (int k = k0; k < k1; k += 4) {
            ull t2[4][2], s2[4][2];
            #pragma unroll
            for (int i = 0; i < 4; i++) {
                float4 t = *(const float4*)&tb[(n0 + i) * CH + k];
                t2[i][0] = packf(t.x, t.y);
                t2[i][1] = packf(t.z, t.w);
            }
            #pragma unroll
            for (int j = 0; j < 4; j++) {
                float4 s = *(const float4*)&sb[(m0 + j) * CH + k];
                s2[j][0] = packf(s.x, s.y);
                s2[j][1] = packf(s.z, s.w);
            }
            #pragma unroll
            for (int i = 0; i < 4; i++)
                #pragma unroll
                for (int j = 0; j < 4; j++) {
                    fma2(c2[i][j], t2[i][0], s2[j][0]);
                    fma2(c2[i][j], t2[i][1], s2[j][1]);
                }
        }
        #pragma unroll
        for (int i = 0; i < 4; i++)
            #pragma unroll
            for (int j = 0; j < 4; j++) {
                float lo, hi;
                unpackf(c2[i][j], lo, hi);
                adjp[g][n0 + i][m0 + j] = lo + hi;
            }
    }
    __syncthreads();
    // deterministic fixed-order reduction of the 4 k-partials
    #pragma unroll
    for (int e = tid; e < 1024; e += 256) {
        int n = e >> 5, m = e & 31;
        adj[n][m] += ((adjp[0][n][m] + adjp[1][n][m]) +
                      (adjp[2][n][m] + adjp[3][n][m]));
    }
    __syncthreads();

    // --- mean / std (ddof=1) over all 1024 entries ---
    {
        float ls = 0.f, lq = 0.f;
        #pragma unroll
        for (int e = tid; e < 1024; e += 256) {
            float a = adj[e >> 5][e & 31];
            ls += a;
            lq = fmaf(a, a, lq);
        }
        #pragma unroll
        for (int o = 16; o; o >>= 1) {
            ls += __shfl_xor_sync(0xFFFFFFFFu, ls, o);
            lq += __shfl_xor_sync(0xFFFFFFFFu, lq, o);
        }
        if (lane == 0) { redS[w] = ls; redQ[w] = lq; }
        __syncthreads();
        if (tid == 0) {
            float S = 0.f, Q = 0.f;
            #pragma unroll
            for (int i = 0; i < 8; i++) { S += redS[i]; Q += redQ[i]; }
            float mean = S * (1.f / 1024.f);
            float var = (Q - S * S * (1.f / 1024.f)) * (1.f / 1023.f);
            stats[0] = mean;
            stats[1] = rsqrtf(var);
        }
        __syncthreads();
    }
    const float mean = stats[0], invstd = stats[1];

    // --- row softmax (warp per 4 rows; lane = column m) ---
    #pragma unroll
    for (int rr = 0; rr < 4; rr++) {
        int n = w * 4 + rr;
        float z = (adj[n][lane] - mean) * invstd;
        float mx = z;
        #pragma unroll
        for (int o = 16; o; o >>= 1) mx = fmaxf(mx, __shfl_xor_sync(0xFFFFFFFFu, mx, o));
        float e = __expf(z - mx);
        float sm = e;
        #pragma unroll
        for (int o = 16; o; o >>= 1) sm += __shfl_xor_sync(0xFFFFFFFFu, sm, o);
        adj[n][lane] = e / sm;
    }
    __syncthreads();

    // --- q[m] = colmean(soft)[m] + 1/32 ---
    if (w == 0) {
        float a = 0.f;
        #pragma unroll
        for (int n = 0; n < 32; n++) a += adj[n][lane];
        qw[lane] = a * (1.f / 32.f) + (1.f / 32.f);
    }
    __syncthreads();

    // --- out[b,c] = sum_m q[m] * s[m,c] ---
    #pragma unroll
    for (int c = tid; c < CH; c += 256) {
        float a = 0.f;
        #pragma unroll
        for (int m = 0; m < 32; m++)
            a = fmaf(qw[m], sb[m * CH + c], a);
        out[b * CH + c] = a;
    }
}

// ---------------------------------------------------------------------------
extern "C" void kernel_launch(void* const* d_in, const int* in_sizes, int n_in,
                              void* d_out, int out_size)
{
    const float* x  = (const float*)d_in[0];
    const float* W1 = (const float*)d_in[1];
    const float* b1 = (const float*)d_in[2];
    const float* W2 = (const float*)d_in[3];
    const float* b2 = (const float*)d_in[4];
    float* out = (float*)d_out;

    k1_pool_prep<<<POOL_BID0 + POOL_BLKS, 256>>>(x, W1, b1, W2, b2);
    k2_gemmT<<<256, 256>>>();
    k3_finale<<<BATCH, 256>>>(out);
}

// round 13
// speedup vs baseline: 1.1083x; 1.1083x over previous
#include <cuda_runtime.h>
#include <cstdint>

// Problem constants
#define BATCH 64
#define NNODE 32
#define CH    512
#define HW    49
#define ROWS  (BATCH * NNODE * CH)     // 1,048,576 pooled rows of 49 floats
#define SROWS (BATCH * NNODE)          // 2048 rows of state / T

// Pooling pipeline: 3-stage TMA-bulk ring, 64-row chunks (12544 B each)
#define CHUNK_ROWS 64
#define CHUNK_BYTES (CHUNK_ROWS * HW * 4)      // 12544, multiple of 16
#define CHUNKS_PER_BLK 16
#define POOL_BLKS (ROWS / (CHUNK_ROWS * CHUNKS_PER_BLK))   // 1024
#define NSTAGE 3
#define UV_BLKS 16
#define POOL_BID0 (64 + UV_BLKS)               // pooling starts at block 80

typedef unsigned long long ull;

// Scratch (device globals; no allocation allowed)
__device__ float g_state[SROWS * CH];  // 4 MB  state[b*32+n][c]
__device__ float g_T[SROWS * CH];      // 4 MB  T = state @ M
__device__ float g_M[CH * CH];         // 1 MB  M = W1^T W2
__device__ float g_u[CH];              // u = W1^T b2
__device__ float g_v[CH];              // v = W2^T b1
__device__ float g_c0;                 // b1 . b2

// ---- packed f32x2 helpers (sm_100+) ----
__device__ __forceinline__ ull dupf(float v) {
    ull r; asm("mov.b64 %0, {%1, %1};" : "=l"(r) : "f"(v)); return r;
}
__device__ __forceinline__ ull packf(float lo, float hi) {
    ull r; asm("mov.b64 %0, {%1, %2};" : "=l"(r) : "f"(lo), "f"(hi)); return r;
}
__device__ __forceinline__ void fma2(ull& d, ull a, ull b) {
    asm("fma.rn.f32x2 %0, %1, %2, %0;" : "+l"(d) : "l"(a), "l"(b));
}
__device__ __forceinline__ void unpackf(ull p, float& lo, float& hi) {
    asm("mov.b64 {%0, %1}, %2;" : "=f"(lo), "=f"(hi) : "l"(p));
}

// ---- mbarrier + bulk-async helpers ----
__device__ __forceinline__ void mbar_init(uint32_t addr, uint32_t cnt) {
    asm volatile("mbarrier.init.shared.b64 [%0], %1;" :: "r"(addr), "r"(cnt) : "memory");
}
__device__ __forceinline__ void mbar_expect_tx(uint32_t addr, uint32_t bytes) {
    asm volatile("mbarrier.arrive.expect_tx.shared.b64 _, [%0], %1;"
                 :: "r"(addr), "r"(bytes) : "memory");
}
__device__ __forceinline__ void mbar_wait(uint32_t addr, uint32_t phase) {
    uint32_t done;
    asm volatile(
        "{\n\t.reg .pred p;\n\t"
        "mbarrier.try_wait.parity.acquire.cta.shared::cta.b64 p, [%1], %2;\n\t"
        "selp.b32 %0, 1, 0, p;\n\t}"
        : "=r"(done) : "r"(addr), "r"(phase) : "memory");
    if (!done) {
        asm volatile(
            "{\n\t.reg .pred P1;\n\t"
            "WL_%=:\n\t"
            "mbarrier.try_wait.parity.acquire.cta.shared::cta.b64 P1, [%0], %1, 0x989680;\n\t"
            "@P1 bra.uni WD_%=;\n\t"
            "bra.uni WL_%=;\n\t"
            "WD_%=:\n\t}"
            :: "r"(addr), "r"(phase) : "memory");
    }
}
__device__ __forceinline__ void bulk_ld(uint32_t dst_smem, const void* src_gmem,
                                        uint32_t bytes, uint32_t mbar) {
    asm volatile(
        "cp.async.bulk.shared::cluster.global.mbarrier::complete_tx::bytes "
        "[%0], [%1], %2, [%3];"
        :: "r"(dst_smem), "l"(src_gmem), "r"(bytes), "r"(mbar) : "memory");
}
__device__ __forceinline__ void fence_proxy_async_cta() {
    asm volatile("fence.proxy.async.shared::cta;" ::: "memory");
}

// ---------------------------------------------------------------------------
// Kernel 1: blocks [0,64)   -> M = W1^T W2 (64x64 tiles)
//           blocks [64,80)  -> u, v (32 columns each); block 64 also c0
//           blocks [80,..)  -> pooling: 3-stage cp.async.bulk pipeline
// ---------------------------------------------------------------------------
__global__ void __launch_bounds__(256) k1_pool_prep(
    const float* __restrict__ x,
    const float* __restrict__ W1, const float* __restrict__ b1,
    const float* __restrict__ W2, const float* __restrict__ b2)
{
    __shared__ __align__(16) union {
        struct { float As[16][64]; float Bs[16][64]; } gemm;          // 8 KB
        struct { float ru[8][33]; float rv[8][33]; } uv;              // ~2 KB
        struct {
            float buf[NSTAGE][CHUNK_ROWS * HW];                       // 37632 B
            unsigned long long mbar[NSTAGE];
        } pool;
    } smem;

    const int bid = blockIdx.x;
    const int tid = threadIdx.x;

    if (bid < 64) {
        // ---- M = W1^T W2 : M[i,j] = sum_k W1[k,i] * W2[k,j] ----
        float (*As)[64] = smem.gemm.As;
        float (*Bs)[64] = smem.gemm.Bs;
        const int j0 = (bid & 7) * 64;
        const int i0 = (bid >> 3) * 64;
        const int lkk = tid >> 4;            // 0..15
        const int lj4 = (tid & 15) * 4;      // 0..60
        const int ty = tid >> 4, tx = tid & 15;
        float acc[4][4];
        #pragma unroll
        for (int i = 0; i < 4; i++)
            #pragma unroll
            for (int j = 0; j < 4; j++) acc[i][j] = 0.f;

        for (int kc = 0; kc < CH; kc += 16) {
            float4 a4 = *(const float4*)&W1[(kc + lkk) * CH + i0 + lj4];
            float4 b4 = *(const float4*)&W2[(kc + lkk) * CH + j0 + lj4];
            *(float4*)&As[lkk][lj4] = a4;
            *(float4*)&Bs[lkk][lj4] = b4;
            __syncthreads();
            #pragma unroll
            for (int kk = 0; kk < 16; kk++) {
                float4 a = *(const float4*)&As[kk][ty * 4];
                float4 b = *(const float4*)&Bs[kk][tx * 4];
                float av[4] = {a.x, a.y, a.z, a.w};
                float bv[4] = {b.x, b.y, b.z, b.w};
                #pragma unroll
                for (int i = 0; i < 4; i++)
                    #pragma unroll
                    for (int j = 0; j < 4; j++)
                        acc[i][j] = fmaf(av[i], bv[j], acc[i][j]);
            }
            __syncthreads();
        }
        #pragma unroll
        for (int i = 0; i < 4; i++) {
            float4 o = make_float4(acc[i][0], acc[i][1], acc[i][2], acc[i][3]);
            *(float4*)&g_M[(i0 + ty * 4 + i) * CH + j0 + tx * 4] = o;
        }
        return;
    }

    if (bid < POOL_BID0) {
        // ---- u/v: 16 blocks, 32 columns each, 8-way d-split ----
        const int j = bid - 64;          // 0..15
        const int i = j * 32 + (tid & 31);
        const int dg = tid >> 5;         // 0..7
        float au = 0.f, av = 0.f;
        #pragma unroll 8
        for (int d = dg; d < CH; d += 8) {
            float bb2 = b2[d], bb1 = b1[d];
            au = fmaf(W1[d * CH + i], bb2, au);
            av = fmaf(W2[d * CH + i], bb1, av);
        }
        smem.uv.ru[dg][tid & 31] = au;
        smem.uv.rv[dg][tid & 31] = av;
        __syncthreads();
        if (tid < 32) {
            float su = 0.f, sv = 0.f;
            #pragma unroll
            for (int g = 0; g < 8; g++) { su += smem.uv.ru[g][tid]; sv += smem.uv.rv[g][tid]; }
            g_u[j * 32 + tid] = su;
            g_v[j * 32 + tid] = sv;
        }
        // c0 = b1.b2 (block 64, warp 1, deterministic lane order)
        if (j == 0 && (tid >> 5) == 1) {
            const int lane = tid & 31;
            float c = 0.f;
            #pragma unroll
            for (int d = lane; d < CH; d += 32) c = fmaf(b1[d], b2[d], c);
            #pragma unroll
            for (int o = 16; o; o >>= 1) c += __shfl_xor_sync(0xFFFFFFFFu, c, o);
            if (lane == 0) g_c0 = c;
        }
        return;
    }

    // ---- Pooling: 3-stage cp.async.bulk pipeline ----
    {
        const int pb = bid - POOL_BID0;                // 0..1023
        const int chunk0 = pb * CHUNKS_PER_BLK;

        uint32_t sbuf[NSTAGE], smb[NSTAGE];
        #pragma unroll
        for (int s = 0; s < NSTAGE; s++) {
            sbuf[s] = (uint32_t)__cvta_generic_to_shared(&smem.pool.buf[s][0]);
            smb[s]  = (uint32_t)__cvta_generic_to_shared(&smem.pool.mbar[s]);
        }

        if (tid == 0) {
            #pragma unroll
            for (int s = 0; s < NSTAGE; s++) mbar_init(smb[s], 1);
            fence_proxy_async_cta();
        }
        __syncthreads();

        auto issue = [&](int c) {
            const int st = c % NSTAGE;
            mbar_expect_tx(smb[st], CHUNK_BYTES);
            bulk_ld(sbuf[st],
                    x + (size_t)(chunk0 + c) * CHUNK_ROWS * HW,
                    CHUNK_BYTES, smb[st]);
        };

        if (tid == 0) { issue(0); issue(1); issue(2); }

        const int row = tid >> 2;       // 0..63
        const int sub = tid & 3;        // quarter-row selector

        #pragma unroll
        for (int c = 0; c < CHUNKS_PER_BLK; c++) {
            mbar_wait(smb[c % NSTAGE], (c / NSTAGE) & 1);

            const float* __restrict__ r = &smem.pool.buf[c % NSTAGE][row * HW];
            float s = 0.f;
            #pragma unroll
            for (int k = sub; k < HW; k += 4) s += r[k];
            s += __shfl_xor_sync(0xFFFFFFFFu, s, 1);
            s += __shfl_xor_sync(0xFFFFFFFFu, s, 2);
            if (sub == 0)
                g_state[(size_t)(chunk0 + c) * CHUNK_ROWS + row] = s * (1.f / 49.f);

            __syncthreads();            // all reads of stage c%NSTAGE done
            if (tid == 0 && c + NSTAGE < CHUNKS_PER_BLK)
                issue(c + NSTAGE);      // refill the stage just drained
        }
    }
}

// ---------------------------------------------------------------------------
// Kernel 2: T = S @ M  (2048x512 @ 512x512)
// 128x64 tiles (128 blocks = 1 wave), 8x4 microtiles, f32x2 packed,
// reg-prefetch double buffer, ONE __syncthreads per 16-wide K chunk.
// ---------------------------------------------------------------------------
__global__ void __launch_bounds__(256) k2_gemmT()
{
    __shared__ __align__(16) float As[2][16][136];  // [buf][k][row], padded
    __shared__ __align__(16) float Bs[2][16][64];   // [buf][k][col]

    const int tid = threadIdx.x;
    const int j0 = (blockIdx.x & 7) * 64;           // over CH (512/64 = 8)
    const int r0 = (blockIdx.x >> 3) * 128;         // over SROWS (2048/128 = 16)

    const int a_i = tid >> 1;                       // 0..127 (row within tile)
    const int a_k = (tid & 1) * 8;                  // 0 or 8
    const int lkk = tid >> 4;                       // 0..15
    const int lj4 = (tid & 15) * 4;
    const int ty = tid >> 4, tx = tid & 15;         // thread: rows ty*8.., cols tx*4..

    ull acc2[4][4];                                 // [i-pair][j]
    #pragma unroll
    for (int ip = 0; ip < 4; ip++)
        #pragma unroll
        for (int j = 0; j < 4; j++) acc2[ip][j] = 0ull;

    const float* __restrict__ srow = &g_state[(size_t)(r0 + a_i) * CH + a_k];
    const float* __restrict__ mrow = &g_M[(size_t)lkk * CH + j0 + lj4];

    // prefetch + stage chunk 0
    float4 pa0 = *(const float4*)(srow + 0);
    float4 pa1 = *(const float4*)(srow + 4);
    float4 pb  = *(const float4*)(mrow + 0);
    As[0][a_k + 0][a_i] = pa0.x; As[0][a_k + 1][a_i] = pa0.y;
    As[0][a_k + 2][a_i] = pa0.z; As[0][a_k + 3][a_i] = pa0.w;
    As[0][a_k + 4][a_i] = pa1.x; As[0][a_k + 5][a_i] = pa1.y;
    As[0][a_k + 6][a_i] = pa1.z; As[0][a_k + 7][a_i] = pa1.w;
    *(float4*)&Bs[0][lkk][lj4] = pb;
    // prefetch chunk 1 into regs
    pa0 = *(const float4*)(srow + 16);
    pa1 = *(const float4*)(srow + 20);
    pb  = *(const float4*)(mrow + 16 * CH);
    __syncthreads();

    #pragma unroll 1
    for (int ci = 0; ci < 32; ci++) {
        const int cur = ci & 1;
        #pragma unroll
        for (int kk = 0; kk < 16; kk++) {
            float4 alo = *(const float4*)&As[cur][kk][ty * 8];
            float4 ahi = *(const float4*)&As[cur][kk][ty * 8 + 4];
            float4 b   = *(const float4*)&Bs[cur][kk][tx * 4];
            ull i2[4] = {packf(alo.x, alo.y), packf(alo.z, alo.w),
                         packf(ahi.x, ahi.y), packf(ahi.z, ahi.w)};
            ull jd[4] = {dupf(b.x), dupf(b.y), dupf(b.z), dupf(b.w)};
            #pragma unroll
            for (int ip = 0; ip < 4; ip++)
                #pragma unroll
                for (int j = 0; j < 4; j++)
                    fma2(acc2[ip][j], i2[ip], jd[j]);
        }
        if (ci + 1 < 32) {
            const int nxt = 1 - cur;
            // stage chunk ci+1 (in regs) into the idle buffer; last reads of
            // that buffer (chunk ci-1) were fenced by the previous sync.
            As[nxt][a_k + 0][a_i] = pa0.x; As[nxt][a_k + 1][a_i] = pa0.y;
            As[nxt][a_k + 2][a_i] = pa0.z; As[nxt][a_k + 3][a_i] = pa0.w;
            As[nxt][a_k + 4][a_i] = pa1.x; As[nxt][a_k + 5][a_i] = pa1.y;
            As[nxt][a_k + 6][a_i] = pa1.z; As[nxt][a_k + 7][a_i] = pa1.w;
            *(float4*)&Bs[nxt][lkk][lj4] = pb;
            if (ci + 2 < 32) {
                const int kc = (ci + 2) * 16;
                pa0 = *(const float4*)(srow + kc);
                pa1 = *(const float4*)(srow + kc + 4);
                pb  = *(const float4*)(mrow + (size_t)kc * CH);
            }
            __syncthreads();   // STS visible; also fences reads of buf[cur]
        }
    }

    // writeback: rows r0 + ty*8 + 2*ip + h, cols j0 + tx*4..+3
    #pragma unroll
    for (int ip = 0; ip < 4; ip++) {
        float lo0, hi0, lo1, hi1, lo2, hi2, lo3, hi3;
        unpackf(acc2[ip][0], lo0, hi0);
        unpackf(acc2[ip][1], lo1, hi1);
        unpackf(acc2[ip][2], lo2, hi2);
        unpackf(acc2[ip][3], lo3, hi3);
        const int rbase = r0 + ty * 8 + ip * 2;
        *(float4*)&g_T[(size_t)rbase * CH + j0 + tx * 4] =
            make_float4(lo0, lo1, lo2, lo3);
        *(float4*)&g_T[(size_t)(rbase + 1) * CH + j0 + tx * 4] =
            make_float4(hi0, hi1, hi2, hi3);
    }
}

// ---------------------------------------------------------------------------
// Kernel 3: one block per batch.  (plain-FFMA R10 version)
//   adj[n,m] = T[b,n,:].S[b,m,:] + su[n] + sv[m] + c0
//   z = (adj - mean)/std(ddof=1); soft = row softmax(z)
//   out[b,c] = sum_m (colmean(soft)[m] + 1/32) * S[b,m,c]
// ---------------------------------------------------------------------------
__global__ void __launch_bounds__(256) k3_finale(float* __restrict__ out)
{
    __shared__ float adj[32][36];
    __shared__ float adjp[4][32][36];
    __shared__ float su[32], sv[32], qw[32];
    __shared__ float redS[8], redQ[8];
    __shared__ float stats[2];

    const int b = blockIdx.x;
    const int tid = threadIdx.x;
    const int w = tid >> 5;
    const int lane = tid & 31;

    const float* sb = g_state + (size_t)(b * NNODE) * CH;
    const float* tb = g_T + (size_t)(b * NNODE) * CH;

    // --- su[n] = s[n].u ; sv[n] = s[n].v  (warp per 4 rows) ---
    #pragma unroll
    for (int rr = 0; rr < 4; rr++) {
        int n = w * 4 + rr;
        const float* srow = sb + n * CH;
        float au = 0.f, av = 0.f;
        for (int k = lane; k < CH; k += 32) {
            float s = srow[k];
            au = fmaf(s, g_u[k], au);
            av = fmaf(s, g_v[k], av);
        }
        #pragma unroll
        for (int o = 16; o; o >>= 1) {
            au += __shfl_xor_sync(0xFFFFFFFFu, au, o);
            av += __shfl_xor_sync(0xFFFFFFFFu, av, o);
        }
        if (lane == 0) { su[n] = au; sv[n] = av; }
    }
    __syncthreads();

    // --- adj bias init ---
    const float c0 = g_c0;
    #pragma unroll
    for (int e = tid; e < 1024; e += 256)
        adj[e >> 5][e & 31] = su[e >> 5] + sv[e & 31] + c0;

    // --- adj partial dots: 4x4 register blocks, k split in 4 ---
    {
        const int rg = tid & 63, g = tid >> 6;
        const int n0 = (rg >> 3) * 4, m0 = (rg & 7) * 4;
        float c[4][4];
        #pragma unroll
        for (int i = 0; i < 4; i++)
            #pragma unroll
            for (int j = 0; j < 4; j++) c[i][j] = 0.f;

        const int k0 = g * 128, k1 = k0 + 128;
        for (int k = k0; k < k1; k += 4) {
            float4 t[4], s[4];
            #pragma unroll
            for (int i = 0; i < 4; i++) t[i] = *(const float4*)&tb[(n0 + i) * CH + k];
            #pragma unroll
            for (int j = 0; j < 4; j++) s[j] = *(const float4*)&sb[(m0 + j) * CH + k];
            #pragma unroll
            for (int i = 0; i < 4; i++)
                #pragma unroll
                for (int j = 0; j < 4; j++) {
                    c[i][j] = fmaf(t[i].x, s[j].x, c[i][j]);
                    c[i][j] = fmaf(t[i].y, s[j].y, c[i][j]);
                    c[i][j] = fmaf(t[i].z, s[j].z, c[i][j]);
                    c[i][j] = fmaf(t[i].w, s[j].w, c[i][j]);
                }
        }
        #pragma unroll
        for (int i = 0; i < 4; i++)
            #pragma unroll
            for (int j = 0; j < 4; j++)
                adjp[g][n0 + i][m0 + j] = c[i][j];
    }
    __syncthreads();
    // deterministic fixed-order reduction of the 4 k-partials
    #pragma unroll
    for (int e = tid; e < 1024; e += 256) {
        int n = e >> 5, m = e & 31;
        adj[n][m] += ((adjp[0][n][m] + adjp[1][n][m]) +
                      (adjp[2][n][m] + adjp[3][n][m]));
    }
    __syncthreads();

    // --- mean / std (ddof=1) over all 1024 entries ---
    {
        float ls = 0.f, lq = 0.f;
        #pragma unroll
        for (int e = tid; e < 1024; e += 256) {
            float a = adj[e >> 5][e & 31];
            ls += a;
            lq = fmaf(a, a, lq);
        }
        #pragma unroll
        for (int o = 16; o; o >>= 1) {
            ls += __shfl_xor_sync(0xFFFFFFFFu, ls, o);
            lq += __shfl_xor_sync(0xFFFFFFFFu, lq, o);
        }
        if (lane == 0) { redS[w] = ls; redQ[w] = lq; }
        __syncthreads();
        if (tid == 0) {
            float S = 0.f, Q = 0.f;
            #pragma unroll
            for (int i = 0; i < 8; i++) { S += redS[i]; Q += redQ[i]; }
            float mean = S * (1.f / 1024.f);
            float var = (Q - S * S * (1.f / 1024.f)) * (1.f / 1023.f);
            stats[0] = mean;
            stats[1] = rsqrtf(var);
        }
        __syncthreads();
    }
    const float mean = stats[0], invstd = stats[1];

    // --- row softmax (warp per 4 rows; lane = column m) ---
    #pragma unroll
    for (int rr = 0; rr < 4; rr++) {
        int n = w * 4 + rr;
        float z = (adj[n][lane] - mean) * invstd;
        float mx = z;
        #pragma unroll
        for (int o = 16; o; o >>= 1) mx = fmaxf(mx, __shfl_xor_sync(0xFFFFFFFFu, mx, o));
        float e = __expf(z - mx);
        float sm = e;
        #pragma unroll
        for (int o = 16; o; o >>= 1) sm += __shfl_xor_sync(0xFFFFFFFFu, sm, o);
        adj[n][lane] = e / sm;
    }
    __syncthreads();

    // --- q[m] = colmean(soft)[m] + 1/32 ---
    if (w == 0) {
        float a = 0.f;
        #pragma unroll
        for (int n = 0; n < 32; n++) a += adj[n][lane];
        qw[lane] = a * (1.f / 32.f) + (1.f / 32.f);
    }
    __syncthreads();

    // --- out[b,c] = sum_m q[m] * s[m,c] ---
    #pragma unroll
    for (int c = tid; c < CH; c += 256) {
        float a = 0.f;
        #pragma unroll
        for (int m = 0; m < 32; m++)
            a = fmaf(qw[m], sb[m * CH + c], a);
        out[b * CH + c] = a;
    }
}

// ---------------------------------------------------------------------------
extern "C" void kernel_launch(void* const* d_in, const int* in_sizes, int n_in,
                              void* d_out, int out_size)
{
    const float* x  = (const float*)d_in[0];
    const float* W1 = (const float*)d_in[1];
    const float* b1 = (const float*)d_in[2];
    const float* W2 = (const float*)d_in[3];
    const float* b2 = (const float*)d_in[4];
    float* out = (float*)d_out;

    k1_pool_prep<<<POOL_BID0 + POOL_BLKS, 256>>>(x, W1, b1, W2, b2);
    k2_gemmT<<<128, 256>>>();
    k3_finale<<<BATCH, 256>>>(out);
}

// round 16
// speedup vs baseline: 1.1275x; 1.0173x over previous
#include <cuda_runtime.h>
#include <cstdint>

// Problem constants
#define BATCH 64
#define NNODE 32
#define CH    512
#define HW    49
#define ROWS  (BATCH * NNODE * CH)     // 1,048,576 pooled rows of 49 floats
#define SROWS (BATCH * NNODE)          // 2048 rows of state / T

// Pooling: persistent blocks, 3-stage TMA-bulk ring, 64-row chunks
#define CHUNK_ROWS 64
#define CHUNK_BYTES (CHUNK_ROWS * HW * 4)      // 12544, multiple of 16
#define NCHUNKS (ROWS / CHUNK_ROWS)            // 16384
#define POOL_BLKS 640                          // persistent: 5/SM x 128 SMs
#define NSTAGE 3
#define UV_BLKS 16
#define POOL_BID0 (64 + UV_BLKS)               // pooling starts at block 80

typedef unsigned long long ull;

// Scratch (device globals; no allocation allowed)
__device__ float g_state[SROWS * CH];  // 4 MB  state[b*32+n][c]
__device__ float g_T[SROWS * CH];      // 4 MB  T = state @ M
__device__ float g_M[CH * CH];         // 1 MB  M = W1^T W2
__device__ float g_u[CH];              // u = W1^T b2
__device__ float g_v[CH];              // v = W2^T b1
__device__ float g_c0;                 // b1 . b2

// ---- packed f32x2 helpers (sm_100+) ----
__device__ __forceinline__ ull dupf(float v) {
    ull r; asm("mov.b64 %0, {%1, %1};" : "=l"(r) : "f"(v)); return r;
}
__device__ __forceinline__ ull packf(float lo, float hi) {
    ull r; asm("mov.b64 %0, {%1, %2};" : "=l"(r) : "f"(lo), "f"(hi)); return r;
}
__device__ __forceinline__ void fma2(ull& d, ull a, ull b) {
    asm("fma.rn.f32x2 %0, %1, %2, %0;" : "+l"(d) : "l"(a), "l"(b));
}
__device__ __forceinline__ void unpackf(ull p, float& lo, float& hi) {
    asm("mov.b64 {%0, %1}, %2;" : "=f"(lo), "=f"(hi) : "l"(p));
}

// ---- mbarrier + bulk-async helpers ----
__device__ __forceinline__ void mbar_init(uint32_t addr, uint32_t cnt) {
    asm volatile("mbarrier.init.shared.b64 [%0], %1;" :: "r"(addr), "r"(cnt) : "memory");
}
__device__ __forceinline__ void mbar_expect_tx(uint32_t addr, uint32_t bytes) {
    asm volatile("mbarrier.arrive.expect_tx.shared.b64 _, [%0], %1;"
                 :: "r"(addr), "r"(bytes) : "memory");
}
__device__ __forceinline__ void mbar_wait(uint32_t addr, uint32_t phase) {
    uint32_t done;
    asm volatile(
        "{\n\t.reg .pred p;\n\t"
        "mbarrier.try_wait.parity.acquire.cta.shared::cta.b64 p, [%1], %2;\n\t"
        "selp.b32 %0, 1, 0, p;\n\t}"
        : "=r"(done) : "r"(addr), "r"(phase) : "memory");
    if (!done) {
        asm volatile(
            "{\n\t.reg .pred P1;\n\t"
            "WL_%=:\n\t"
            "mbarrier.try_wait.parity.acquire.cta.shared::cta.b64 P1, [%0], %1, 0x989680;\n\t"
            "@P1 bra.uni WD_%=;\n\t"
            "bra.uni WL_%=;\n\t"
            "WD_%=:\n\t}"
            :: "r"(addr), "r"(phase) : "memory");
    }
}
__device__ __forceinline__ void bulk_ld(uint32_t dst_smem, const void* src_gmem,
                                        uint32_t bytes, uint32_t mbar) {
    asm volatile(
        "cp.async.bulk.shared::cluster.global.mbarrier::complete_tx::bytes "
        "[%0], [%1], %2, [%3];"
        :: "r"(dst_smem), "l"(src_gmem), "r"(bytes), "r"(mbar) : "memory");
}
__device__ __forceinline__ void fence_proxy_async_cta() {
    asm volatile("fence.proxy.async.shared::cta;" ::: "memory");
}

// ---------------------------------------------------------------------------
// Kernel 1: blocks [0,64)   -> M = W1^T W2 (64x64 tiles)
//           blocks [64,80)  -> u, v (32 columns each); block 64 also c0
//           blocks [80,720) -> pooling: persistent, 3-stage bulk pipeline
// ---------------------------------------------------------------------------
__global__ void __launch_bounds__(256) k1_pool_prep(
    const float* __restrict__ x,
    const float* __restrict__ W1, const float* __restrict__ b1,
    const float* __restrict__ W2, const float* __restrict__ b2)
{
    __shared__ __align__(16) union {
        struct { float As[16][64]; float Bs[16][64]; } gemm;          // 8 KB
        struct { float ru[8][33]; float rv[8][33]; } uv;              // ~2 KB
        struct {
            float buf[NSTAGE][CHUNK_ROWS * HW];                       // 37632 B
            unsigned long long mbar[NSTAGE];
        } pool;
    } smem;

    const int bid = blockIdx.x;
    const int tid = threadIdx.x;

    if (bid < 64) {
        // ---- M = W1^T W2 : M[i,j] = sum_k W1[k,i] * W2[k,j] ----
        float (*As)[64] = smem.gemm.As;
        float (*Bs)[64] = smem.gemm.Bs;
        const int j0 = (bid & 7) * 64;
        const int i0 = (bid >> 3) * 64;
        const int lkk = tid >> 4;            // 0..15
        const int lj4 = (tid & 15) * 4;      // 0..60
        const int ty = tid >> 4, tx = tid & 15;
        float acc[4][4];
        #pragma unroll
        for (int i = 0; i < 4; i++)
            #pragma unroll
            for (int j = 0; j < 4; j++) acc[i][j] = 0.f;

        for (int kc = 0; kc < CH; kc += 16) {
            float4 a4 = *(const float4*)&W1[(kc + lkk) * CH + i0 + lj4];
            float4 b4 = *(const float4*)&W2[(kc + lkk) * CH + j0 + lj4];
            *(float4*)&As[lkk][lj4] = a4;
            *(float4*)&Bs[lkk][lj4] = b4;
            __syncthreads();
            #pragma unroll
            for (int kk = 0; kk < 16; kk++) {
                float4 a = *(const float4*)&As[kk][ty * 4];
                float4 b = *(const float4*)&Bs[kk][tx * 4];
                float av[4] = {a.x, a.y, a.z, a.w};
                float bv[4] = {b.x, b.y, b.z, b.w};
                #pragma unroll
                for (int i = 0; i < 4; i++)
                    #pragma unroll
                    for (int j = 0; j < 4; j++)
                        acc[i][j] = fmaf(av[i], bv[j], acc[i][j]);
            }
            __syncthreads();
        }
        #pragma unroll
        for (int i = 0; i < 4; i++) {
            float4 o = make_float4(acc[i][0], acc[i][1], acc[i][2], acc[i][3]);
            *(float4*)&g_M[(i0 + ty * 4 + i) * CH + j0 + tx * 4] = o;
        }
        return;
    }

    if (bid < POOL_BID0) {
        // ---- u/v: 16 blocks, 32 columns each, 8-way d-split ----
        const int j = bid - 64;          // 0..15
        const int i = j * 32 + (tid & 31);
        const int dg = tid >> 5;         // 0..7
        float au = 0.f, av = 0.f;
        #pragma unroll 8
        for (int d = dg; d < CH; d += 8) {
            float bb2 = b2[d], bb1 = b1[d];
            au = fmaf(W1[d * CH + i], bb2, au);
            av = fmaf(W2[d * CH + i], bb1, av);
        }
        smem.uv.ru[dg][tid & 31] = au;
        smem.uv.rv[dg][tid & 31] = av;
        __syncthreads();
        if (tid < 32) {
            float su = 0.f, sv = 0.f;
            #pragma unroll
            for (int g = 0; g < 8; g++) { su += smem.uv.ru[g][tid]; sv += smem.uv.rv[g][tid]; }
            g_u[j * 32 + tid] = su;
            g_v[j * 32 + tid] = sv;
        }
        // c0 = b1.b2 (block 64, warp 1, deterministic lane order)
        if (j == 0 && (tid >> 5) == 1) {
            const int lane = tid & 31;
            float c = 0.f;
            #pragma unroll
            for (int d = lane; d < CH; d += 32) c = fmaf(b1[d], b2[d], c);
            #pragma unroll
            for (int o = 16; o; o >>= 1) c += __shfl_xor_sync(0xFFFFFFFFu, c, o);
            if (lane == 0) g_c0 = c;
        }
        return;
    }

    // ---- Pooling: persistent blocks, 3-stage cp.async.bulk pipeline ----
    {
        const int pb = bid - POOL_BID0;                // 0..POOL_BLKS-1

        uint32_t sbuf[NSTAGE], smb[NSTAGE];
        #pragma unroll
        for (int s = 0; s < NSTAGE; s++) {
            sbuf[s] = (uint32_t)__cvta_generic_to_shared(&smem.pool.buf[s][0]);
            smb[s]  = (uint32_t)__cvta_generic_to_shared(&smem.pool.mbar[s]);
        }

        if (tid == 0) {
            #pragma unroll
            for (int s = 0; s < NSTAGE; s++) mbar_init(smb[s], 1);
            fence_proxy_async_cta();
        }
        __syncthreads();

        // iteration it handles chunk pb + it*POOL_BLKS in stage it%NSTAGE
        auto issue_it = [&](int it) {
            const int cc = pb + it * POOL_BLKS;
            if (cc < NCHUNKS) {
                const int st = it % NSTAGE;
                mbar_expect_tx(smb[st], CHUNK_BYTES);
                bulk_ld(sbuf[st],
                        x + (size_t)cc * CHUNK_ROWS * HW,
                        CHUNK_BYTES, smb[st]);
            }
        };

        if (tid == 0) { issue_it(0); issue_it(1); issue_it(2); }

        const int row = tid >> 2;       // 0..63
        const int sub = tid & 3;        // quarter-row selector

        for (int it = 0, c = pb; c < NCHUNKS; it++, c += POOL_BLKS) {
            const int st = it % NSTAGE;
            mbar_wait(smb[st], (it / NSTAGE) & 1);

            const float* __restrict__ r = &smem.pool.buf[st][row * HW];
            float s = 0.f;
            #pragma unroll
            for (int k = sub; k < HW; k += 4) s += r[k];
            s += __shfl_xor_sync(0xFFFFFFFFu, s, 1);
            s += __shfl_xor_sync(0xFFFFFFFFu, s, 2);
            if (sub == 0)
                g_state[(size_t)c * CHUNK_ROWS + row] = s * (1.f / 49.f);

            __syncthreads();            // all reads of stage st done
            if (tid == 0) issue_it(it + NSTAGE);
        }
    }
}

// ---------------------------------------------------------------------------
// Kernel 2: T = S @ M  (2048x512 @ 512x512)
// 64x64 tiles (256 blocks, 2/SM), 4x4 microtiles, f32x2 packed,
// reg-prefetch double buffer, ONE __syncthreads per 16-wide K chunk.
// ---------------------------------------------------------------------------
__global__ void __launch_bounds__(256) k2_gemmT()
{
    __shared__ __align__(16) float As[2][16][68];   // [buf][k][row], padded
    __shared__ __align__(16) float Bs[2][16][64];   // [buf][k][col]

    const int tid = threadIdx.x;
    const int j0 = (blockIdx.x & 7) * 64;           // over CH (512/64 = 8)
    const int r0 = (blockIdx.x >> 3) * 64;          // over SROWS (2048/64 = 32)

    const int a_i = tid >> 2;                       // 0..63 (row within tile)
    const int a_k = (tid & 3) * 4;                  // 0,4,8,12
    const int lkk = tid >> 4;                       // 0..15
    const int lj4 = (tid & 15) * 4;
    const int ty = tid >> 4, tx = tid & 15;         // rows ty*4.., cols tx*4..

    ull acc2[2][4];                                 // [i-pair][j]
    #pragma unroll
    for (int ip = 0; ip < 2; ip++)
        #pragma unroll
        for (int j = 0; j < 4; j++) acc2[ip][j] = 0ull;

    const float* __restrict__ srow = &g_state[(size_t)(r0 + a_i) * CH + a_k];
    const float* __restrict__ mrow = &g_M[(size_t)lkk * CH + j0 + lj4];

    // stage chunk 0
    float4 pa = *(const float4*)(srow + 0);
    float4 pb = *(const float4*)(mrow + 0);
    As[0][a_k + 0][a_i] = pa.x; As[0][a_k + 1][a_i] = pa.y;
    As[0][a_k + 2][a_i] = pa.z; As[0][a_k + 3][a_i] = pa.w;
    *(float4*)&Bs[0][lkk][lj4] = pb;
    // prefetch chunk 1 into regs
    pa = *(const float4*)(srow + 16);
    pb = *(const float4*)(mrow + 16 * CH);
    __syncthreads();

    #pragma unroll 1
    for (int ci = 0; ci < 32; ci++) {
        const int cur = ci & 1;
        #pragma unroll
        for (int kk = 0; kk < 16; kk++) {
            float4 a = *(const float4*)&As[cur][kk][ty * 4];
            float4 b = *(const float4*)&Bs[cur][kk][tx * 4];
            ull i2[2] = {packf(a.x, a.y), packf(a.z, a.w)};
            ull jd[4] = {dupf(b.x), dupf(b.y), dupf(b.z), dupf(b.w)};
            #pragma unroll
            for (int ip = 0; ip < 2; ip++)
                #pragma unroll
                for (int j = 0; j < 4; j++)
                    fma2(acc2[ip][j], i2[ip], jd[j]);
        }
        if (ci + 1 < 32) {
            const int nxt = 1 - cur;
            As[nxt][a_k + 0][a_i] = pa.x; As[nxt][a_k + 1][a_i] = pa.y;
            As[nxt][a_k + 2][a_i] = pa.z; As[nxt][a_k + 3][a_i] = pa.w;
            *(float4*)&Bs[nxt][lkk][lj4] = pb;
            if (ci + 2 < 32) {
                const int kc = (ci + 2) * 16;
                pa = *(const float4*)(srow + kc);
                pb = *(const float4*)(mrow + (size_t)kc * CH);
            }
            __syncthreads();   // STS visible; also fences reads of buf[cur]
        }
    }

    // writeback: rows r0 + ty*4 + 2*ip + h, cols j0 + tx*4..+3
    #pragma unroll
    for (int ip = 0; ip < 2; ip++) {
        float lo0, hi0, lo1, hi1, lo2, hi2, lo3, hi3;
        unpackf(acc2[ip][0], lo0, hi0);
        unpackf(acc2[ip][1], lo1, hi1);
        unpackf(acc2[ip][2], lo2, hi2);
        unpackf(acc2[ip][3], lo3, hi3);
        const int rbase = r0 + ty * 4 + ip * 2;
        *(float4*)&g_T[(size_t)rbase * CH + j0 + tx * 4] =
            make_float4(lo0, lo1, lo2, lo3);
        *(float4*)&g_T[(size_t)(rbase + 1) * CH + j0 + tx * 4] =
            make_float4(hi0, hi1, hi2, hi3);
    }
}

// ---------------------------------------------------------------------------
// Kernel 3: one block per batch.  (plain-FFMA)
//   adj[n,m] = T[b,n,:].S[b,m,:] + su[n] + sv[m] + c0
//   z = (adj - mean)/std(ddof=1); soft = row softmax(z)
//   out[b,c] = sum_m (colmean(soft)[m] + 1/32) * S[b,m,c]
// ---------------------------------------------------------------------------
__global__ void __launch_bounds__(256) k3_finale(float* __restrict__ out)
{
    __shared__ float adj[32][36];
    __shared__ float adjp[4][32][36];
    __shared__ float su[32], sv[32], qw[32];
    __shared__ float redS[8], redQ[8];
    __shared__ float stats[2];

    const int b = blockIdx.x;
    const int tid = threadIdx.x;
    const int w = tid >> 5;
    const int lane = tid & 31;

    const float* sb = g_state + (size_t)(b * NNODE) * CH;
    const float* tb = g_T + (size_t)(b * NNODE) * CH;

    // --- su[n] = s[n].u ; sv[n] = s[n].v  (warp per 4 rows) ---
    #pragma unroll
    for (int rr = 0; rr < 4; rr++) {
        int n = w * 4 + rr;
        const float* srow = sb + n * CH;
        float au = 0.f, av = 0.f;
        for (int k = lane; k < CH; k += 32) {
            float s = srow[k];
            au = fmaf(s, g_u[k], au);
            av = fmaf(s, g_v[k], av);
        }
        #pragma unroll
        for (int o = 16; o; o >>= 1) {
            au += __shfl_xor_sync(0xFFFFFFFFu, au, o);
            av += __shfl_xor_sync(0xFFFFFFFFu, av, o);
        }
        if (lane == 0) { su[n] = au; sv[n] = av; }
    }
    __syncthreads();

    // --- adj bias init ---
    const float c0 = g_c0;
    #pragma unroll
    for (int e = tid; e < 1024; e += 256)
        adj[e >> 5][e & 31] = su[e >> 5] + sv[e & 31] + c0;

    // --- adj partial dots: 4x4 register blocks, k split in 4 ---
    {
        const int rg = tid & 63, g = tid >> 6;
        const int n0 = (rg >> 3) * 4, m0 = (rg & 7) * 4;
        float c[4][4];
        #pragma unroll
        for (int i = 0; i < 4; i++)
            #pragma unroll
            for (int j = 0; j < 4; j++) c[i][j] = 0.f;

        const int k0 = g * 128, k1 = k0 + 128;
        for (int k = k0; k < k1; k += 4) {
            float4 t[4], s[4];
            #pragma unroll
            for (int i = 0; i < 4; i++) t[i] = *(const float4*)&tb[(n0 + i) * CH + k];
            #pragma unroll
            for (int j = 0; j < 4; j++) s[j] = *(const float4*)&sb[(m0 + j) * CH + k];
            #pragma unroll
            for (int i = 0; i < 4; i++)
                #pragma unroll
                for (int j = 0; j < 4; j++) {
                    c[i][j] = fmaf(t[i].x, s[j].x, c[i][j]);
                    c[i][j] = fmaf(t[i].y, s[j].y, c[i][j]);
                    c[i][j] = fmaf(t[i].z, s[j].z, c[i][j]);
                    c[i][j] = fmaf(t[i].w, s[j].w, c[i][j]);
                }
        }
        #pragma unroll
        for (int i = 0; i < 4; i++)
            #pragma unroll
            for (int j = 0; j < 4; j++)
                adjp[g][n0 + i][m0 + j] = c[i][j];
    }
    __syncthreads();
    // deterministic fixed-order reduction of the 4 k-partials
    #pragma unroll
    for (int e = tid; e < 1024; e += 256) {
        int n = e >> 5, m = e & 31;
        adj[n][m] += ((adjp[0][n][m] + adjp[1][n][m]) +
                      (adjp[2][n][m] + adjp[3][n][m]));
    }
    __syncthreads();

    // --- mean / std (ddof=1) over all 1024 entries ---
    {
        float ls = 0.f, lq = 0.f;
        #pragma unroll
        for (int e = tid; e < 1024; e += 256) {
            float a = adj[e >> 5][e & 31];
            ls += a;
            lq = fmaf(a, a, lq);
        }
        #pragma unroll
        for (int o = 16; o; o >>= 1) {
            ls += __shfl_xor_sync(0xFFFFFFFFu, ls, o);
            lq += __shfl_xor_sync(0xFFFFFFFFu, lq, o);
        }
        if (lane == 0) { redS[w] = ls; redQ[w] = lq; }
        __syncthreads();
        if (tid == 0) {
            float S = 0.f, Q = 0.f;
            #pragma unroll
            for (int i = 0; i < 8; i++) { S += redS[i]; Q += redQ[i]; }
            float mean = S * (1.f / 1024.f);
            float var = (Q - S * S * (1.f / 1024.f)) * (1.f / 1023.f);
            stats[0] = mean;
            stats[1] = rsqrtf(var);
        }
        __syncthreads();
    }
    const float mean = stats[0], invstd = stats[1];

    // --- row softmax (warp per 4 rows; lane = column m) ---
    #pragma unroll
    for (int rr = 0; rr < 4; rr++) {
        int n = w * 4 + rr;
        float z = (adj[n][lane] - mean) * invstd;
        float mx = z;
        #pragma unroll
        for (int o = 16; o; o >>= 1) mx = fmaxf(mx, __shfl_xor_sync(0xFFFFFFFFu, mx, o));
        float e = __expf(z - mx);
        float sm = e;
        #pragma unroll
        for (int o = 16; o; o >>= 1) sm += __shfl_xor_sync(0xFFFFFFFFu, sm, o);
        adj[n][lane] = e / sm;
    }
    __syncthreads();

    // --- q[m] = colmean(soft)[m] + 1/32 ---
    if (w == 0) {
        float a = 0.f;
        #pragma unroll
        for (int n = 0; n < 32; n++) a += adj[n][lane];
        qw[lane] = a * (1.f / 32.f) + (1.f / 32.f);
    }
    __syncthreads();

    // --- out[b,c] = sum_m q[m] * s[m,c] ---
    #pragma unroll
    for (int c = tid; c < CH; c += 256) {
        float a = 0.f;
        #pragma unroll
        for (int m = 0; m < 32; m++)
            a = fmaf(qw[m], sb[m * CH + c], a);
        out[b * CH + c] = a;
    }
}

// ---------------------------------------------------------------------------
extern "C" void kernel_launch(void* const* d_in, const int* in_sizes, int n_in,
                              void* d_out, int out_size)
{
    const float* x  = (const float*)d_in[0];
    const float* W1 = (const float*)d_in[1];
    const float* b1 = (const float*)d_in[2];
    const float* W2 = (const float*)d_in[3];
    const float* b2 = (const float*)d_in[4];
    float* out = (float*)d_out;

    k1_pool_prep<<<POOL_BID0 + POOL_BLKS, 256>>>(x, W1, b1, W2, b2);
    k2_gemmT<<<256, 256>>>();
    k3_finale<<<BATCH, 256>>>(out);
}